// round 4
// baseline (speedup 1.0000x reference)
#include <cuda_runtime.h>

// GridToGraphConverter: B=4, C=16, H=W=512
//  out layout (float32, concatenated):
//   [0, NF)            node_features  (B*HW, C)
//   [NF, NF+E)         edge_index src row
//   [NF+E, NF+2E)      edge_index dst row
//   [NF+2E, NF+2E+2E)  edge_attr (E, 2)
// edge_index / edge offsets generated analytically (grid-8 structure).

#define Wd 512
#define Hd 512
#define HWd (Wd * Hd)
#define Cc 16
#define Bb 4
#define NFSZ (Bb * HWd * Cc)        // 16777216
#define Ed 2091012
#define SS 516                       // smem row stride (floats)

__global__ __launch_bounds__(512, 2) void g2g_kernel(const float* __restrict__ grid,
                                                     float* __restrict__ out) {
    // Transpose staging: sm[c][node_in_row], stride SS.
    __shared__ float sm[Cc * SS];

    const int tid = threadIdx.x;        // column w, 0..511
    const int h = blockIdx.x;           // row
    const int lane = tid & 31;
    const int n = h * Wd + tid;

    const bool hasUp = (h > 0);
    const bool hasDn = (h < Hd - 1);
    const bool hasL = (tid > 0);
    const bool hasR = (tid < Wd - 1);

    // Clamped offsets (garbage lands in never-emitted slots).
    const int rowUp = hasUp ? n - Wd : n;
    const int rowDn = hasDn ? n + Wd : n;
    const int colL = hasL ? tid - 1 : tid;   // used only by lane 0
    const int colR = hasR ? tid + 1 : tid;   // used only by lane 31
    const int baseMid = h * Wd;
    const int baseUp = hasUp ? (h - 1) * Wd : baseMid;
    const int baseDn = hasDn ? (h + 1) * Wd : baseMid;

    float acc[8];
#pragma unroll
    for (int k = 0; k < 8; k++) acc[k] = 0.0f;

    for (int b = 0; b < Bb; b++) {
        const float* pb = grid + (size_t)b * (Cc * HWd);
#pragma unroll 4
        for (int c = 0; c < Cc; c++) {
            const float* p = pb + (size_t)c * HWd;
            float own = p[n];
            float up = p[rowUp];
            float dn = p[rowDn];
            sm[c * SS + tid] = own;   // stash for coalesced transpose write

            // Halo via shuffles; warp-edge lanes fall back to clamped scalar LDG.
            float mL = __shfl_up_sync(0xffffffffu, own, 1);
            float uL = __shfl_up_sync(0xffffffffu, up, 1);
            float dL = __shfl_up_sync(0xffffffffu, dn, 1);
            float mR = __shfl_down_sync(0xffffffffu, own, 1);
            float uR = __shfl_down_sync(0xffffffffu, up, 1);
            float dR = __shfl_down_sync(0xffffffffu, dn, 1);
            if (lane == 0) {
                mL = p[baseMid + colL];
                uL = p[baseUp + colL];
                dL = p[baseDn + colL];
            }
            if (lane == 31) {
                mR = p[baseMid + colR];
                uR = p[baseUp + colR];
                dR = p[baseDn + colR];
            }

            acc[0] += fabsf(own - uL);
            acc[1] += fabsf(own - up);
            acc[2] += fabsf(own - uR);
            acc[3] += fabsf(own - mL);
            acc[4] += fabsf(own - mR);
            acc[5] += fabsf(own - dL);
            acc[6] += fabsf(own - dn);
            acc[7] += fabsf(own - dR);
        }
        __syncthreads();
        // Coalesced node_features write for this batch:
        // 512 nodes * 16 channels contiguous at (b*HW + h*512)*16.
        float* dst = out + (size_t)b * HWd * Cc + (size_t)h * Wd * Cc;
#pragma unroll
        for (int j = 0; j < 4; j++) {
            int f = (tid + j * 512) * 4;    // flat float index in row tile
            int nn = f >> 4;                // local node
            int c = f & 15;                 // channel (multiple of 4)
            float4 v;
            v.x = sm[(c + 0) * SS + nn];
            v.y = sm[(c + 1) * SS + nn];
            v.z = sm[(c + 2) * SS + nn];
            v.w = sm[(c + 3) * SS + nn];
            *(float4*)(dst + f) = v;
        }
        __syncthreads();
    }

    // ---- Emit edges (index + attr) for this thread's node ----
    const float SQ2 = 1.41421356237309515f;
    const float dist[8] = {SQ2, 1.0f, SQ2, 1.0f, 1.0f, SQ2, 1.0f, SQ2};
    const int dnk[8] = {-513, -512, -511, -1, 1, 511, 512, 513};
    const float inv64 = 1.0f / 64.0f;

    float* eiS = out + NFSZ;
    float* eiD = out + NFSZ + Ed;
    float* ea  = out + NFSZ + 2 * Ed;

    // boundary rows: 5W-4 edges; interior rows: 8W-6.
    const int rowBase = (h == 0) ? 0 : (5 * Wd - 4) + (h - 1) * (8 * Wd - 6);
    const bool boundaryRow = (h == 0) || (h == Hd - 1);
    int within;
    if (boundaryRow)
        within = (tid == 0) ? 0 : 3 + (tid - 1) * 5;
    else
        within = (tid == 0) ? 0 : 5 + (tid - 1) * 8;
    int e = rowBase + within;

    bool val[8] = {hasUp && hasL, hasUp, hasUp && hasR,
                   hasL, hasR,
                   hasDn && hasL, hasDn, hasDn && hasR};
#pragma unroll
    for (int k = 0; k < 8; k++) {
        if (val[k]) {
            eiS[e] = (float)n;
            eiD[e] = (float)(n + dnk[k]);
            ea[2 * e]     = dist[k];
            ea[2 * e + 1] = acc[k] * inv64;
            e++;
        }
    }
}

extern "C" void kernel_launch(void* const* d_in, const int* in_sizes, int n_in,
                              void* d_out, int out_size) {
    const float* grid = (const float*)d_in[0];
    float* out = (float*)d_out;
    // one block per row: 512 blocks x 512 threads = 1 thread per node
    g2g_kernel<<<Hd, Wd>>>(grid, out);
}

// round 5
// speedup vs baseline: 1.2913x; 1.2913x over previous
#include <cuda_runtime.h>

// GridToGraphConverter: B=4, C=16, H=W=512
//  out layout (float32, concatenated):
//   [0, NF)            node_features  (B*HW, C)
//   [NF, NF+E)         edge_index src row
//   [NF+E, NF+2E)      edge_index dst row
//   [NF+2E, NF+2E+2E)  edge_attr (E, 2)
// edge_index / edge offsets generated analytically (grid-8 structure).
//
// Parallelization: quad of 4 threads shares a 4-node group; each quad thread
// accumulates 4 of the 16 channels (x4 batches = 16 plane-iterations of
// 3x float4 LDG), then a shfl_xor butterfly sums the quad and each lane
// emits one node's edges.

#define Wd 512
#define Hd 512
#define HWd (Wd * Hd)
#define Cc 16
#define Bb 4
#define NFSZ (Bb * HWd * Cc)        // 16777216
#define Ed 2091012
#define SS 260                       // smem stride (256-node tile + pad)

__global__ __launch_bounds__(256, 4) void g2g_kernel(const float* __restrict__ grid,
                                                     float* __restrict__ out) {
    __shared__ float sm[Cc * SS];    // transpose staging [c][node_in_half_row]

    const int tid = threadIdx.x;
    const int h = blockIdx.x >> 1;          // row
    const int half = blockIdx.x & 1;        // half-row
    const int q = tid & 3;                  // channel quad id
    const int lane = tid & 31;
    const int col = half * 256 + tid;       // this thread's emission column
    const int wg = half * 256 + (tid & ~3); // first column of 4-node group
    const int n0 = h * Wd + wg;             // first node of group

    const bool hasUp = (h > 0);
    const bool hasDn = (h < Hd - 1);
    const bool hasL = (wg > 0);
    const bool hasR = (wg < Wd - 4);

    const int oUp = hasUp ? n0 - Wd : n0;
    const int oDn = hasDn ? n0 + Wd : n0;
    // clamped fallback offsets for warp-edge lanes (values unused if invalid)
    const int oLm = hasL ? n0 - 1 : n0;
    const int oLu = hasL ? oUp - 1 : oUp;
    const int oLd = hasL ? oDn - 1 : oDn;
    const int oRm = hasR ? n0 + 4 : n0;
    const int oRu = hasR ? oUp + 4 : oUp;
    const int oRd = hasR ? oDn + 4 : oDn;

    float acc[4][8];
#pragma unroll
    for (int i = 0; i < 4; i++)
#pragma unroll
        for (int k = 0; k < 8; k++) acc[i][k] = 0.0f;

    for (int b = 0; b < Bb; b++) {
        const float* pb = grid + (size_t)b * (Cc * HWd);
#pragma unroll
        for (int ci = 0; ci < 4; ci++) {
            const int c = q * 4 + ci;           // this thread's channel
            const float* p = pb + c * HWd;
            float4 ow = *(const float4*)(p + n0);
            float4 up = *(const float4*)(p + oUp);
            float4 dn = *(const float4*)(p + oDn);
            *(float4*)&sm[c * SS + (tid & ~3)] = ow;   // stash for transpose

            // halo via intra-warp shuffles (quad-stride 4 = same channel,
            // adjacent node group); warp-edge lanes fall back to LDG.
            float mL = __shfl_up_sync(0xffffffffu, ow.w, 4);
            float uL = __shfl_up_sync(0xffffffffu, up.w, 4);
            float dL = __shfl_up_sync(0xffffffffu, dn.w, 4);
            float mR = __shfl_down_sync(0xffffffffu, ow.x, 4);
            float uR = __shfl_down_sync(0xffffffffu, up.x, 4);
            float dR = __shfl_down_sync(0xffffffffu, dn.x, 4);
            if (lane < 4) {
                mL = p[oLm];
                uL = p[oLu];
                dL = p[oLd];
            }
            if (lane >= 28) {
                mR = p[oRm];
                uR = p[oRu];
                dR = p[oRd];
            }

            float u[6] = {uL, up.x, up.y, up.z, up.w, uR};
            float m[6] = {mL, ow.x, ow.y, ow.z, ow.w, mR};
            float d[6] = {dL, dn.x, dn.y, dn.z, dn.w, dR};
#pragma unroll
            for (int i = 0; i < 4; i++) {
                float o = m[i + 1];
                acc[i][0] += fabsf(o - u[i]);
                acc[i][1] += fabsf(o - u[i + 1]);
                acc[i][2] += fabsf(o - u[i + 2]);
                acc[i][3] += fabsf(o - m[i]);
                acc[i][4] += fabsf(o - m[i + 2]);
                acc[i][5] += fabsf(o - d[i]);
                acc[i][6] += fabsf(o - d[i + 1]);
                acc[i][7] += fabsf(o - d[i + 2]);
            }
        }
        __syncthreads();
        // Coalesced node_features write: 256 nodes * 16 channels contiguous.
        float* dst = out + (size_t)b * HWd * Cc
                         + ((size_t)h * Wd + half * 256) * Cc;
#pragma unroll
        for (int j = 0; j < 4; j++) {
            int f = (tid + j * 256) * 4;    // flat float index in tile
            int nn = f >> 4;                // local node
            int c = f & 15;                 // channel (multiple of 4)
            float4 v;
            v.x = sm[(c + 0) * SS + nn];
            v.y = sm[(c + 1) * SS + nn];
            v.z = sm[(c + 2) * SS + nn];
            v.w = sm[(c + 3) * SS + nn];
            *(float4*)(dst + f) = v;
        }
        __syncthreads();
    }

    // ---- Quad butterfly reduce: every lane gets full 64-plane sums ----
#pragma unroll
    for (int i = 0; i < 4; i++)
#pragma unroll
        for (int k = 0; k < 8; k++) {
            acc[i][k] += __shfl_xor_sync(0xffffffffu, acc[i][k], 1);
            acc[i][k] += __shfl_xor_sync(0xffffffffu, acc[i][k], 2);
        }

    // This thread emits node i = q of its group (node index = h*512 + col).
    float a[8];
#pragma unroll
    for (int k = 0; k < 8; k++) {
        float v01 = (q & 1) ? acc[1][k] : acc[0][k];
        float v23 = (q & 1) ? acc[3][k] : acc[2][k];
        a[k] = (q & 2) ? v23 : v01;
    }

    const float SQ2 = 1.41421356237309515f;
    const float dist[8] = {SQ2, 1.0f, SQ2, 1.0f, 1.0f, SQ2, 1.0f, SQ2};
    const int dnk[8] = {-513, -512, -511, -1, 1, 511, 512, 513};
    const float inv64 = 1.0f / 64.0f;

    float* eiS = out + NFSZ;
    float* eiD = out + NFSZ + Ed;
    float* ea  = out + NFSZ + 2 * Ed;

    // boundary rows: 5W-4 edges; interior rows: 8W-6.
    const int rowBase = (h == 0) ? 0 : (5 * Wd - 4) + (h - 1) * (8 * Wd - 6);
    const bool boundaryRow = (h == 0) || (h == Hd - 1);
    int within;
    if (boundaryRow)
        within = (col == 0) ? 0 : 3 + (col - 1) * 5;
    else
        within = (col == 0) ? 0 : 5 + (col - 1) * 8;
    int e = rowBase + within;

    const int n = h * Wd + col;
    const bool vL = (col > 0);
    const bool vR = (col < Wd - 1);
    bool val[8] = {hasUp && vL, hasUp, hasUp && vR,
                   vL, vR,
                   hasDn && vL, hasDn, hasDn && vR};
#pragma unroll
    for (int k = 0; k < 8; k++) {
        if (val[k]) {
            eiS[e] = (float)n;
            eiD[e] = (float)(n + dnk[k]);
            ea[2 * e]     = dist[k];
            ea[2 * e + 1] = a[k] * inv64;
            e++;
        }
    }
}

extern "C" void kernel_launch(void* const* d_in, const int* in_sizes, int n_in,
                              void* d_out, int out_size) {
    const float* grid = (const float*)d_in[0];
    float* out = (float*)d_out;
    // 1024 blocks x 256 threads: each block = half a grid row
    g2g_kernel<<<1024, 256>>>(grid, out);
}